// round 1
// baseline (speedup 1.0000x reference)
#include <cuda_runtime.h>
#include <cstdint>

#define B_   16
#define C_   256
#define SEQ_ 4096
#define NQKV 768

// ---------------- scratch (static device globals; no allocation) ------------
__device__ float g_qkv [(size_t)B_ * SEQ_ * NQKV]; // (b, s, [q|k|v]) 192 MB
__device__ float g_attn[(size_t)B_ * SEQ_ * C_];   // (b, s, c)        64 MB
__device__ float g_tmp [(size_t)B_ * SEQ_ * C_];   // (b, s, c)        64 MB

// ---------------- packed f32x2 helpers --------------------------------------
__device__ __forceinline__ void fma2(unsigned long long& d,
                                     unsigned long long a,
                                     unsigned long long b) {
    asm("fma.rn.f32x2 %0, %1, %2, %3;" : "=l"(d) : "l"(a), "l"(b), "l"(d));
}
__device__ __forceinline__ unsigned long long pack2(float x, float y) {
    unsigned long long r;
    asm("mov.b64 %0, {%1, %2};"
        : "=l"(r) : "r"(__float_as_uint(x)), "r"(__float_as_uint(y)));
    return r;
}
__device__ __forceinline__ float2 unpack2(unsigned long long v) {
    unsigned int lo, hi;
    asm("mov.b64 {%0, %1}, %2;" : "=r"(lo), "=r"(hi) : "l"(v));
    return make_float2(__uint_as_float(lo), __uint_as_float(hi));
}

// ============================================================================
// GEMM1: qkv[b,s,n] = sum_k x[b,k,s] * W[k,n] + bias[n]
//   A is K-major in gmem (x is (b, C, seq)) -> direct As[k][s] tile loads.
//   Block tile 128(M=s) x 128(N) x 16(K); thread micro-tile 8x8 via f32x2.
// ============================================================================
__global__ __launch_bounds__(256) void gemm_qkv_kernel(
    const float* __restrict__ x,
    const float* __restrict__ wq,  const float* __restrict__ bq,
    const float* __restrict__ wkv, const float* __restrict__ bkv)
{
    const int BK = 16;
    __shared__ float As[16][128];
    __shared__ float Bs[16][128];

    int b  = blockIdx.z;
    int n0 = blockIdx.x * 128;          // 0..640 (6 blocks)
    int s0 = blockIdx.y * 128;

    const float* W;  const float* bias; int ldw, wn0;
    if (n0 < 256) { W = wq;  bias = bq;  ldw = 256; wn0 = n0;        }
    else          { W = wkv; bias = bkv; ldw = 512; wn0 = n0 - 256;  }

    const float* Ab = x + (size_t)b * C_ * SEQ_;

    int tid = threadIdx.x;
    int tx = tid & 15, ty = tid >> 4;
    int m_off = ty * 8, n_off = tx * 8;

    unsigned long long acc[8][4];
    #pragma unroll
    for (int i = 0; i < 8; i++)
        #pragma unroll
        for (int j = 0; j < 4; j++) acc[i][j] = 0ull;

    for (int k0 = 0; k0 < C_; k0 += BK) {
        #pragma unroll
        for (int r = 0; r < 2; r++) {
            int idx = tid + r * 256;
            int k = idx >> 5, c4 = (idx & 31) << 2;
            *(float4*)&As[k][c4] =
                *(const float4*)(Ab + (size_t)(k0 + k) * SEQ_ + s0 + c4);
            *(float4*)&Bs[k][c4] =
                *(const float4*)(W + (size_t)(k0 + k) * ldw + wn0 + c4);
        }
        __syncthreads();
        #pragma unroll
        for (int kk = 0; kk < BK; kk++) {
            float4 a0 = *(float4*)&As[kk][m_off];
            float4 a1 = *(float4*)&As[kk][m_off + 4];
            float4 b0 = *(float4*)&Bs[kk][n_off];
            float4 b1 = *(float4*)&Bs[kk][n_off + 4];
            unsigned long long bp[4] = { pack2(b0.x, b0.y), pack2(b0.z, b0.w),
                                         pack2(b1.x, b1.y), pack2(b1.z, b1.w) };
            float am[8] = {a0.x, a0.y, a0.z, a0.w, a1.x, a1.y, a1.z, a1.w};
            #pragma unroll
            for (int mi = 0; mi < 8; mi++) {
                unsigned long long ad = pack2(am[mi], am[mi]);
                #pragma unroll
                for (int nj = 0; nj < 4; nj++) fma2(acc[mi][nj], ad, bp[nj]);
            }
        }
        __syncthreads();
    }

    float bv[8];
    #pragma unroll
    for (int j = 0; j < 8; j++) bv[j] = bias[wn0 + n_off + j];

    #pragma unroll
    for (int mi = 0; mi < 8; mi++) {
        size_t row = ((size_t)b * SEQ_ + s0 + m_off + mi) * NQKV + n0 + n_off;
        #pragma unroll
        for (int nj = 0; nj < 4; nj++) {
            float2 v = unpack2(acc[mi][nj]);
            v.x += bv[2 * nj]; v.y += bv[2 * nj + 1];
            *(float2*)(g_qkv + row + 2 * nj) = v;
        }
    }
}

// ============================================================================
// Attention: per token t, 4x4 attention over heads. One warp per token.
//   Lane l owns dims {l, l+32} of each head.
// ============================================================================
__global__ __launch_bounds__(256) void attn_kernel()
{
    int warp = threadIdx.x >> 5, l = threadIdx.x & 31;
    int t = blockIdx.x * 8 + warp;      // 0 .. B*SEQ-1
    const float* base = g_qkv + (size_t)t * NQKV;

    float q0[4], q1[4], k0v[4], k1v[4];
    #pragma unroll
    for (int n = 0; n < 4; n++) {
        q0[n]  = base[n * 64 + l];
        q1[n]  = base[n * 64 + 32 + l];
        k0v[n] = base[256 + n * 64 + l];
        k1v[n] = base[256 + n * 64 + 32 + l];
    }

    float s[16];
    #pragma unroll
    for (int n = 0; n < 4; n++)
        #pragma unroll
        for (int m = 0; m < 4; m++)
            s[n * 4 + m] = q0[n] * k0v[m] + q1[n] * k1v[m];

    #pragma unroll
    for (int off = 16; off > 0; off >>= 1)
        #pragma unroll
        for (int i = 0; i < 16; i++)
            s[i] += __shfl_xor_sync(0xffffffffu, s[i], off);

    float w[16];
    #pragma unroll
    for (int n = 0; n < 4; n++) {
        float p0 = s[n*4+0] * 0.125f, p1 = s[n*4+1] * 0.125f;
        float p2 = s[n*4+2] * 0.125f, p3 = s[n*4+3] * 0.125f;
        float mx = fmaxf(fmaxf(p0, p1), fmaxf(p2, p3));
        float e0 = __expf(p0 - mx), e1 = __expf(p1 - mx);
        float e2 = __expf(p2 - mx), e3 = __expf(p3 - mx);
        float inv = 1.0f / (e0 + e1 + e2 + e3);
        w[n*4+0] = e0 * inv; w[n*4+1] = e1 * inv;
        w[n*4+2] = e2 * inv; w[n*4+3] = e3 * inv;
    }

    float o0[4] = {0.f,0.f,0.f,0.f}, o1[4] = {0.f,0.f,0.f,0.f};
    #pragma unroll
    for (int m = 0; m < 4; m++) {
        float v0 = base[512 + m * 64 + l];
        float v1 = base[512 + m * 64 + 32 + l];
        #pragma unroll
        for (int n = 0; n < 4; n++) {
            o0[n] += w[n * 4 + m] * v0;
            o1[n] += w[n * 4 + m] * v1;
        }
    }
    float* dst = g_attn + (size_t)t * C_;
    #pragma unroll
    for (int n = 0; n < 4; n++) {
        dst[n * 64 + l]      = o0[n];
        dst[n * 64 + 32 + l] = o1[n];
    }
}

// ============================================================================
// GEMM2: tmp[b,s,n] = sum_k attn[b,s,k] * wo[k,n] + bo[n]
//   A is M-major in gmem -> transpose-load into As[k][s] (pad to 132: k4
//   groups hit distinct bank pairs, 16B row alignment kept for LDS.128).
// ============================================================================
__global__ __launch_bounds__(256) void gemm_out_kernel(
    const float* __restrict__ wo, const float* __restrict__ bo)
{
    const int BK = 16;
    __shared__ float As[16][132];
    __shared__ float Bs[16][128];

    int b  = blockIdx.z;
    int n0 = blockIdx.x * 128;          // 0 or 128
    int s0 = blockIdx.y * 128;
    const float* Ab = g_attn + (size_t)b * SEQ_ * C_;

    int tid = threadIdx.x;
    int tx = tid & 15, ty = tid >> 4;
    int m_off = ty * 8, n_off = tx * 8;

    unsigned long long acc[8][4];
    #pragma unroll
    for (int i = 0; i < 8; i++)
        #pragma unroll
        for (int j = 0; j < 4; j++) acc[i][j] = 0ull;

    for (int k0 = 0; k0 < C_; k0 += BK) {
        #pragma unroll
        for (int r = 0; r < 2; r++) {
            int idx = tid + r * 256;
            int ss = idx >> 2;              // 0..127
            int k4 = (idx & 3) << 2;        // 0,4,8,12
            float4 v = *(const float4*)(Ab + (size_t)(s0 + ss) * C_ + k0 + k4);
            As[k4 + 0][ss] = v.x; As[k4 + 1][ss] = v.y;
            As[k4 + 2][ss] = v.z; As[k4 + 3][ss] = v.w;
            int k = idx >> 5, n4 = (idx & 31) << 2;
            *(float4*)&Bs[k][n4] =
                *(const float4*)(wo + (size_t)(k0 + k) * C_ + n0 + n4);
        }
        __syncthreads();
        #pragma unroll
        for (int kk = 0; kk < BK; kk++) {
            float4 a0 = *(float4*)&As[kk][m_off];
            float4 a1 = *(float4*)&As[kk][m_off + 4];
            float4 b0 = *(float4*)&Bs[kk][n_off];
            float4 b1 = *(float4*)&Bs[kk][n_off + 4];
            unsigned long long bp[4] = { pack2(b0.x, b0.y), pack2(b0.z, b0.w),
                                         pack2(b1.x, b1.y), pack2(b1.z, b1.w) };
            float am[8] = {a0.x, a0.y, a0.z, a0.w, a1.x, a1.y, a1.z, a1.w};
            #pragma unroll
            for (int mi = 0; mi < 8; mi++) {
                unsigned long long ad = pack2(am[mi], am[mi]);
                #pragma unroll
                for (int nj = 0; nj < 4; nj++) fma2(acc[mi][nj], ad, bp[nj]);
            }
        }
        __syncthreads();
    }

    float bv[8];
    #pragma unroll
    for (int j = 0; j < 8; j++) bv[j] = bo[n0 + n_off + j];

    #pragma unroll
    for (int mi = 0; mi < 8; mi++) {
        size_t row = ((size_t)b * SEQ_ + s0 + m_off + mi) * C_ + n0 + n_off;
        #pragma unroll
        for (int nj = 0; nj < 4; nj++) {
            float2 v = unpack2(acc[mi][nj]);
            v.x += bv[2 * nj]; v.y += bv[2 * nj + 1];
            *(float2*)(g_tmp + row + 2 * nj) = v;
        }
    }
}

// ============================================================================
// Transpose: (b, s, c) -> (b, c, s), fully coalesced via 32x33 smem tile.
// ============================================================================
__global__ void transpose_kernel(float* __restrict__ out)
{
    __shared__ float tile[32][33];
    int b = blockIdx.z;
    const float* in = g_tmp + (size_t)b * SEQ_ * C_;
    float* o = out + (size_t)b * C_ * SEQ_;
    int s0 = blockIdx.x * 32, c0 = blockIdx.y * 32;
    int x = threadIdx.x, y = threadIdx.y;

    #pragma unroll
    for (int i = 0; i < 32; i += 8)
        tile[y + i][x] = in[(size_t)(s0 + y + i) * C_ + c0 + x];
    __syncthreads();
    #pragma unroll
    for (int i = 0; i < 32; i += 8)
        o[(size_t)(c0 + y + i) * SEQ_ + s0 + x] = tile[x][y + i];
}

// ============================================================================
extern "C" void kernel_launch(void* const* d_in, const int* in_sizes, int n_in,
                              void* d_out, int out_size)
{
    const float* x   = (const float*)d_in[0];
    const float* wq  = (const float*)d_in[1];
    const float* bq  = (const float*)d_in[2];
    const float* wkv = (const float*)d_in[3];
    const float* bkv = (const float*)d_in[4];
    const float* wo  = (const float*)d_in[5];
    const float* bo  = (const float*)d_in[6];
    float* out = (float*)d_out;

    gemm_qkv_kernel<<<dim3(6, 32, 16), 256>>>(x, wq, bq, wkv, bkv);
    attn_kernel<<<(B_ * SEQ_) / 8, 256>>>();
    gemm_out_kernel<<<dim3(2, 32, 16), 256>>>(wo, bo);
    transpose_kernel<<<dim3(SEQ_ / 32, C_ / 32, B_), dim3(32, 8)>>>(out);
}

// round 2
// speedup vs baseline: 1.5595x; 1.5595x over previous
#include <cuda_runtime.h>
#include <cuda_bf16.h>
#include <cstdint>

#define B_   16
#define C_   256
#define SEQ_ 4096
#define NQKV 768

// ---------------- scratch (static device globals; no allocation) ------------
__device__ float g_qkv [(size_t)B_ * SEQ_ * NQKV]; // (b, s, [q|k|v])
__device__ float g_attn[(size_t)B_ * SEQ_ * C_];   // (b, s, c)

// ---------------- mma.sync helper -------------------------------------------
__device__ __forceinline__ void mma_bf16(float* acc, const uint32_t* a,
                                         const uint32_t* b) {
    asm volatile(
        "mma.sync.aligned.m16n8k16.row.col.f32.bf16.bf16.f32 "
        "{%0,%1,%2,%3}, {%4,%5,%6,%7}, {%8,%9}, {%0,%1,%2,%3};"
        : "+f"(acc[0]), "+f"(acc[1]), "+f"(acc[2]), "+f"(acc[3])
        : "r"(a[0]), "r"(a[1]), "r"(a[2]), "r"(a[3]), "r"(b[0]), "r"(b[1]));
}

__device__ __forceinline__ void split_bf16(float f, __nv_bfloat16& h,
                                           __nv_bfloat16& l) {
    h = __float2bfloat16(f);
    l = __float2bfloat16(f - __bfloat162float(h));
}

// ============================================================================
// GEMM1: qkv[b,s,n] = sum_k x[b,k,s] * W[k,n] + bias[n]
//   bf16x3 split mma. Block 128(M=s) x 128(N), K-step 16, 8 warps (2x4).
//   x is K-major: A tile loads are coalesced along s directly.
// ============================================================================
__global__ __launch_bounds__(256) void gemm_qkv_mma(
    const float* __restrict__ x,
    const float* __restrict__ wq,  const float* __restrict__ bq,
    const float* __restrict__ wkv, const float* __restrict__ bkv)
{
    __shared__ __nv_bfloat16 Ah[128][18], Al[128][18];
    __shared__ __nv_bfloat16 Bh[128][18], Bl[128][18];

    int b  = blockIdx.z;
    int n0 = blockIdx.x * 128;
    int s0 = blockIdx.y * 128;

    const float* W; const float* bias; int ldw, wn0;
    if (n0 < 256) { W = wq;  bias = bq;  ldw = 256; wn0 = n0;       }
    else          { W = wkv; bias = bkv; ldw = 512; wn0 = n0 - 256; }

    const float* Ab = x + (size_t)b * C_ * SEQ_;

    int tid  = threadIdx.x;
    int warp = tid >> 5, lane = tid & 31;
    int g = lane >> 2, tg = lane & 3;
    int wm = (warp & 1) * 64, wn = (warp >> 1) * 32;

    // per-thread tile-load coords (2 float4 per tile per thread)
    int k_a[2], c4_a[2];
    #pragma unroll
    for (int r = 0; r < 2; r++) {
        int idx = tid + r * 256;
        k_a[r] = idx >> 5; c4_a[r] = (idx & 31) << 2;
    }

    float acc[4][4][4];
    #pragma unroll
    for (int i = 0; i < 4; i++)
        #pragma unroll
        for (int j = 0; j < 4; j++)
            #pragma unroll
            for (int q = 0; q < 4; q++) acc[i][j][q] = 0.f;

    // prefetch first tile into regs
    float4 va[2], vb[2];
    #pragma unroll
    for (int r = 0; r < 2; r++) {
        va[r] = *(const float4*)(Ab + (size_t)k_a[r] * SEQ_ + s0 + c4_a[r]);
        vb[r] = *(const float4*)(W  + (size_t)k_a[r] * ldw  + wn0 + c4_a[r]);
    }

    for (int k0 = 0; k0 < C_; k0 += 16) {
        // store current tile to smem (with hi/lo split)
        #pragma unroll
        for (int r = 0; r < 2; r++) {
            const float* fa = &va[r].x;
            const float* fb = &vb[r].x;
            #pragma unroll
            for (int j = 0; j < 4; j++) {
                __nv_bfloat16 h, l;
                split_bf16(fa[j], h, l);
                Ah[c4_a[r] + j][k_a[r]] = h; Al[c4_a[r] + j][k_a[r]] = l;
                split_bf16(fb[j], h, l);
                Bh[c4_a[r] + j][k_a[r]] = h; Bl[c4_a[r] + j][k_a[r]] = l;
            }
        }
        __syncthreads();

        // prefetch next tile
        if (k0 + 16 < C_) {
            #pragma unroll
            for (int r = 0; r < 2; r++) {
                va[r] = *(const float4*)(Ab + (size_t)(k0 + 16 + k_a[r]) * SEQ_ + s0 + c4_a[r]);
                vb[r] = *(const float4*)(W  + (size_t)(k0 + 16 + k_a[r]) * ldw  + wn0 + c4_a[r]);
            }
        }

        // fragments
        uint32_t ah[4][4], al[4][4], bh[4][2], bl[4][2];
        #pragma unroll
        for (int mt = 0; mt < 4; mt++) {
            int m = wm + mt * 16;
            ah[mt][0] = *(const uint32_t*)&Ah[m + g][2 * tg];
            ah[mt][1] = *(const uint32_t*)&Ah[m + g + 8][2 * tg];
            ah[mt][2] = *(const uint32_t*)&Ah[m + g][2 * tg + 8];
            ah[mt][3] = *(const uint32_t*)&Ah[m + g + 8][2 * tg + 8];
            al[mt][0] = *(const uint32_t*)&Al[m + g][2 * tg];
            al[mt][1] = *(const uint32_t*)&Al[m + g + 8][2 * tg];
            al[mt][2] = *(const uint32_t*)&Al[m + g][2 * tg + 8];
            al[mt][3] = *(const uint32_t*)&Al[m + g + 8][2 * tg + 8];
        }
        #pragma unroll
        for (int nt = 0; nt < 4; nt++) {
            int n = wn + nt * 8;
            bh[nt][0] = *(const uint32_t*)&Bh[n + g][2 * tg];
            bh[nt][1] = *(const uint32_t*)&Bh[n + g][2 * tg + 8];
            bl[nt][0] = *(const uint32_t*)&Bl[n + g][2 * tg];
            bl[nt][1] = *(const uint32_t*)&Bl[n + g][2 * tg + 8];
        }

        #pragma unroll
        for (int mt = 0; mt < 4; mt++)
            #pragma unroll
            for (int nt = 0; nt < 4; nt++) {
                mma_bf16(acc[mt][nt], ah[mt], bh[nt]);
                mma_bf16(acc[mt][nt], ah[mt], bl[nt]);
                mma_bf16(acc[mt][nt], al[mt], bh[nt]);
            }
        __syncthreads();
    }

    // epilogue: add bias, store fp32 qkv
    #pragma unroll
    for (int nt = 0; nt < 4; nt++) {
        int nloc = wn + nt * 8 + 2 * tg;           // within 128-wide tile
        float b0 = bias[wn0 + nloc], b1 = bias[wn0 + nloc + 1];
        #pragma unroll
        for (int mt = 0; mt < 4; mt++) {
            int s = s0 + wm + mt * 16 + g;
            size_t r0 = ((size_t)b * SEQ_ + s) * NQKV + n0 + nloc;
            size_t r1 = ((size_t)b * SEQ_ + s + 8) * NQKV + n0 + nloc;
            *(float2*)(g_qkv + r0) =
                make_float2(acc[mt][nt][0] + b0, acc[mt][nt][1] + b1);
            *(float2*)(g_qkv + r1) =
                make_float2(acc[mt][nt][2] + b0, acc[mt][nt][3] + b1);
        }
    }
}

// ============================================================================
// Attention: per token, 4x4 over heads. One warp per token.
// ============================================================================
__global__ __launch_bounds__(256) void attn_kernel()
{
    int warp = threadIdx.x >> 5, l = threadIdx.x & 31;
    int t = blockIdx.x * 8 + warp;
    const float* base = g_qkv + (size_t)t * NQKV;

    float q0[4], q1[4], k0v[4], k1v[4];
    #pragma unroll
    for (int n = 0; n < 4; n++) {
        q0[n]  = base[n * 64 + l];
        q1[n]  = base[n * 64 + 32 + l];
        k0v[n] = base[256 + n * 64 + l];
        k1v[n] = base[256 + n * 64 + 32 + l];
    }

    float s[16];
    #pragma unroll
    for (int n = 0; n < 4; n++)
        #pragma unroll
        for (int m = 0; m < 4; m++)
            s[n * 4 + m] = q0[n] * k0v[m] + q1[n] * k1v[m];

    #pragma unroll
    for (int off = 16; off > 0; off >>= 1)
        #pragma unroll
        for (int i = 0; i < 16; i++)
            s[i] += __shfl_xor_sync(0xffffffffu, s[i], off);

    float w[16];
    #pragma unroll
    for (int n = 0; n < 4; n++) {
        float p0 = s[n*4+0] * 0.125f, p1 = s[n*4+1] * 0.125f;
        float p2 = s[n*4+2] * 0.125f, p3 = s[n*4+3] * 0.125f;
        float mx = fmaxf(fmaxf(p0, p1), fmaxf(p2, p3));
        float e0 = __expf(p0 - mx), e1 = __expf(p1 - mx);
        float e2 = __expf(p2 - mx), e3 = __expf(p3 - mx);
        float inv = 1.0f / (e0 + e1 + e2 + e3);
        w[n*4+0] = e0 * inv; w[n*4+1] = e1 * inv;
        w[n*4+2] = e2 * inv; w[n*4+3] = e3 * inv;
    }

    float o0[4] = {0.f,0.f,0.f,0.f}, o1[4] = {0.f,0.f,0.f,0.f};
    #pragma unroll
    for (int m = 0; m < 4; m++) {
        float v0 = base[512 + m * 64 + l];
        float v1 = base[512 + m * 64 + 32 + l];
        #pragma unroll
        for (int n = 0; n < 4; n++) {
            o0[n] += w[n * 4 + m] * v0;
            o1[n] += w[n * 4 + m] * v1;
        }
    }
    float* dst = g_attn + (size_t)t * C_;
    #pragma unroll
    for (int n = 0; n < 4; n++) {
        dst[n * 64 + l]      = o0[n];
        dst[n * 64 + 32 + l] = o1[n];
    }
}

// ============================================================================
// GEMM2 (+fused transpose): out[b, n, s] = sum_k attn[b,s,k]*wo[k,n] + bo[n]
//   bf16x3 split mma; epilogue stores directly in transposed (b,c,s) layout.
// ============================================================================
__global__ __launch_bounds__(256) void gemm_out_mma(
    const float* __restrict__ wo, const float* __restrict__ bo,
    float* __restrict__ out)
{
    __shared__ __nv_bfloat16 Ah[128][18], Al[128][18];
    __shared__ __nv_bfloat16 Bh[128][18], Bl[128][18];

    int b  = blockIdx.z;
    int n0 = blockIdx.x * 128;          // 0 or 128
    int s0 = blockIdx.y * 128;
    const float* Ab = g_attn + (size_t)b * SEQ_ * C_;

    int tid  = threadIdx.x;
    int warp = tid >> 5, lane = tid & 31;
    int g = lane >> 2, tg = lane & 3;
    int wm = (warp & 1) * 64, wn = (warp >> 1) * 32;

    // A load coords: attn is [s][k] row-major: float4 along k
    int s_a[2], k4_a[2];
    // B load coords: wo is [k][n]: float4 along n (transposed into Bs[n][k])
    int k_b[2], n4_b[2];
    #pragma unroll
    for (int r = 0; r < 2; r++) {
        int idx = tid + r * 256;
        s_a[r]  = idx >> 2;  k4_a[r] = (idx & 3) << 2;
        k_b[r]  = idx >> 5;  n4_b[r] = (idx & 31) << 2;
    }

    float acc[4][4][4];
    #pragma unroll
    for (int i = 0; i < 4; i++)
        #pragma unroll
        for (int j = 0; j < 4; j++)
            #pragma unroll
            for (int q = 0; q < 4; q++) acc[i][j][q] = 0.f;

    float4 va[2], vb[2];
    #pragma unroll
    for (int r = 0; r < 2; r++) {
        va[r] = *(const float4*)(Ab + (size_t)(s0 + s_a[r]) * C_ + k4_a[r]);
        vb[r] = *(const float4*)(wo + (size_t)k_b[r] * C_ + n0 + n4_b[r]);
    }

    for (int k0 = 0; k0 < C_; k0 += 16) {
        #pragma unroll
        for (int r = 0; r < 2; r++) {
            const float* fa = &va[r].x;
            const float* fb = &vb[r].x;
            #pragma unroll
            for (int j = 0; j < 4; j++) {
                __nv_bfloat16 h, l;
                split_bf16(fa[j], h, l);
                Ah[s_a[r]][k4_a[r] + j] = h; Al[s_a[r]][k4_a[r] + j] = l;
                split_bf16(fb[j], h, l);
                Bh[n4_b[r] + j][k_b[r]] = h; Bl[n4_b[r] + j][k_b[r]] = l;
            }
        }
        __syncthreads();

        if (k0 + 16 < C_) {
            #pragma unroll
            for (int r = 0; r < 2; r++) {
                va[r] = *(const float4*)(Ab + (size_t)(s0 + s_a[r]) * C_ + k0 + 16 + k4_a[r]);
                vb[r] = *(const float4*)(wo + (size_t)(k0 + 16 + k_b[r]) * C_ + n0 + n4_b[r]);
            }
        }

        uint32_t ah[4][4], al[4][4], bh[4][2], bl[4][2];
        #pragma unroll
        for (int mt = 0; mt < 4; mt++) {
            int m = wm + mt * 16;
            ah[mt][0] = *(const uint32_t*)&Ah[m + g][2 * tg];
            ah[mt][1] = *(const uint32_t*)&Ah[m + g + 8][2 * tg];
            ah[mt][2] = *(const uint32_t*)&Ah[m + g][2 * tg + 8];
            ah[mt][3] = *(const uint32_t*)&Ah[m + g + 8][2 * tg + 8];
            al[mt][0] = *(const uint32_t*)&Al[m + g][2 * tg];
            al[mt][1] = *(const uint32_t*)&Al[m + g + 8][2 * tg];
            al[mt][2] = *(const uint32_t*)&Al[m + g][2 * tg + 8];
            al[mt][3] = *(const uint32_t*)&Al[m + g + 8][2 * tg + 8];
        }
        #pragma unroll
        for (int nt = 0; nt < 4; nt++) {
            int n = wn + nt * 8;
            bh[nt][0] = *(const uint32_t*)&Bh[n + g][2 * tg];
            bh[nt][1] = *(const uint32_t*)&Bh[n + g][2 * tg + 8];
            bl[nt][0] = *(const uint32_t*)&Bl[n + g][2 * tg];
            bl[nt][1] = *(const uint32_t*)&Bl[n + g][2 * tg + 8];
        }

        #pragma unroll
        for (int mt = 0; mt < 4; mt++)
            #pragma unroll
            for (int nt = 0; nt < 4; nt++) {
                mma_bf16(acc[mt][nt], ah[mt], bh[nt]);
                mma_bf16(acc[mt][nt], ah[mt], bl[nt]);
                mma_bf16(acc[mt][nt], al[mt], bh[nt]);
            }
        __syncthreads();
    }

    // fused-transpose epilogue: out[b][c][s], c = n index, s = m index.
    float* ob = out + (size_t)b * C_ * SEQ_;
    #pragma unroll
    for (int nt = 0; nt < 4; nt++) {
        int c = n0 + wn + nt * 8 + 2 * tg;
        float b0 = bo[c], b1 = bo[c + 1];
        #pragma unroll
        for (int mt = 0; mt < 4; mt++) {
            int s = s0 + wm + mt * 16 + g;
            ob[(size_t)c       * SEQ_ + s]     = acc[mt][nt][0] + b0;
            ob[(size_t)(c + 1) * SEQ_ + s]     = acc[mt][nt][1] + b1;
            ob[(size_t)c       * SEQ_ + s + 8] = acc[mt][nt][2] + b0;
            ob[(size_t)(c + 1) * SEQ_ + s + 8] = acc[mt][nt][3] + b1;
        }
    }
}

// ============================================================================
extern "C" void kernel_launch(void* const* d_in, const int* in_sizes, int n_in,
                              void* d_out, int out_size)
{
    const float* x   = (const float*)d_in[0];
    const float* wq  = (const float*)d_in[1];
    const float* bq  = (const float*)d_in[2];
    const float* wkv = (const float*)d_in[3];
    const float* bkv = (const float*)d_in[4];
    const float* wo  = (const float*)d_in[5];
    const float* bo  = (const float*)d_in[6];
    float* out = (float*)d_out;

    gemm_qkv_mma<<<dim3(6, 32, 16), 256>>>(x, wq, bq, wkv, bkv);
    attn_kernel<<<(B_ * SEQ_) / 8, 256>>>();
    gemm_out_mma<<<dim3(2, 32, 16), 256>>>(wo, bo, out);
}

// round 3
// speedup vs baseline: 2.3208x; 1.4882x over previous
#include <cuda_runtime.h>
#include <cuda_bf16.h>
#include <cstdint>

#define B_   16
#define C_   256
#define SEQ_ 4096
#define NQKV 768
#define NKT  8          // K=256 / BK=32

// ---------------- scratch (static device globals) ---------------------------
__device__ __nv_bfloat16 g_xh [(size_t)B_ * C_ * SEQ_];
__device__ __nv_bfloat16 g_xl [(size_t)B_ * C_ * SEQ_];
__device__ __nv_bfloat16 g_wh [(size_t)C_ * NQKV];      // combined [k][768]
__device__ __nv_bfloat16 g_wl [(size_t)C_ * NQKV];
__device__ __nv_bfloat16 g_woh[(size_t)C_ * C_];
__device__ __nv_bfloat16 g_wol[(size_t)C_ * C_];
__device__ float         g_qkv[(size_t)B_ * SEQ_ * NQKV];
__device__ __nv_bfloat16 g_ah [(size_t)B_ * SEQ_ * C_]; // attn out hi
__device__ __nv_bfloat16 g_al [(size_t)B_ * SEQ_ * C_]; // attn out lo

// ---------------- PTX helpers ------------------------------------------------
__device__ __forceinline__ void mma_bf16(float* acc, const uint32_t* a,
                                         const uint32_t* b) {
    asm volatile(
        "mma.sync.aligned.m16n8k16.row.col.f32.bf16.bf16.f32 "
        "{%0,%1,%2,%3}, {%4,%5,%6,%7}, {%8,%9}, {%0,%1,%2,%3};"
        : "+f"(acc[0]), "+f"(acc[1]), "+f"(acc[2]), "+f"(acc[3])
        : "r"(a[0]), "r"(a[1]), "r"(a[2]), "r"(a[3]), "r"(b[0]), "r"(b[1]));
}
__device__ __forceinline__ void ldsm4(uint32_t* r, uint32_t addr) {
    asm volatile("ldmatrix.sync.aligned.m8n8.x4.shared.b16 {%0,%1,%2,%3}, [%4];"
        : "=r"(r[0]), "=r"(r[1]), "=r"(r[2]), "=r"(r[3]) : "r"(addr));
}
__device__ __forceinline__ void ldsm4t(uint32_t* r, uint32_t addr) {
    asm volatile("ldmatrix.sync.aligned.m8n8.x4.trans.shared.b16 {%0,%1,%2,%3}, [%4];"
        : "=r"(r[0]), "=r"(r[1]), "=r"(r[2]), "=r"(r[3]) : "r"(addr));
}
__device__ __forceinline__ void cpa16(uint32_t dst, const void* src) {
    asm volatile("cp.async.cg.shared.global [%0], [%1], 16;" :: "r"(dst), "l"(src));
}
#define CP_COMMIT()  asm volatile("cp.async.commit_group;")
#define CP_WAIT1()   asm volatile("cp.async.wait_group 1;")

// ============================================================================
// Split pass: fp32 -> bf16 hi/lo  (vectorized, grid-stride not needed: exact)
// ============================================================================
__global__ void split_f4(const float4* __restrict__ in,
                         uint2* __restrict__ oh, uint2* __restrict__ ol, int n4)
{
    int i = blockIdx.x * 256 + threadIdx.x;
    if (i >= n4) return;
    float4 v = in[i];
    __nv_bfloat162 h01 = __float22bfloat162_rn(make_float2(v.x, v.y));
    __nv_bfloat162 h23 = __float22bfloat162_rn(make_float2(v.z, v.w));
    float2 hf01 = __bfloat1622float2(h01);
    float2 hf23 = __bfloat1622float2(h23);
    __nv_bfloat162 l01 = __float22bfloat162_rn(make_float2(v.x - hf01.x, v.y - hf01.y));
    __nv_bfloat162 l23 = __float22bfloat162_rn(make_float2(v.z - hf23.x, v.w - hf23.y));
    uint2 ho, lo;
    ho.x = *(uint32_t*)&h01; ho.y = *(uint32_t*)&h23;
    lo.x = *(uint32_t*)&l01; lo.y = *(uint32_t*)&l23;
    oh[i] = ho; ol[i] = lo;
}

__global__ void split_wqkv(const float* __restrict__ wq,
                           const float* __restrict__ wkv)
{
    int idx = blockIdx.x * 256 + threadIdx.x;      // 256*768
    int k = idx / NQKV, n = idx % NQKV;
    float f = (n < 256) ? wq[k * 256 + n] : wkv[k * 512 + (n - 256)];
    __nv_bfloat16 h = __float2bfloat16(f);
    g_wh[idx] = h;
    g_wl[idx] = __float2bfloat16(f - __bfloat162float(h));
}

// ============================================================================
// GEMM1: qkv[b,s,n] = sum_k x[b,k,s]*W[k,n] + bias[n]
//   A = x (stored [k][s])  -> trans tile, ldmatrix.trans
//   B = W (stored [k][n])  -> trans tile, ldmatrix.trans
//   128x128 block, BK=32, 8 warps (2x4), bf16x3 mma, cp.async 2-stage.
// ============================================================================
__device__ __forceinline__ void fill_trans_pair(
    uint32_t st, const __nv_bfloat16* srcH, const __nv_bfloat16* srcL,
    int ld, int col0, int k0, int tid)
{
    // tile: 32 rows(k) x 128 cols, 256B rows, 16 chunks; swizzle chunk^(row&7)
    #pragma unroll
    for (int i = 0; i < 2; i++) {
        int idx2 = (i << 8) + tid;
        int row = idx2 >> 4, chunk = idx2 & 15;
        uint32_t doff = row * 256 + ((chunk ^ (row & 7)) << 4);
        size_t soff = (size_t)(k0 + row) * ld + col0 + chunk * 8;
        cpa16(st + doff,        srcH + soff);
        cpa16(st + 8192 + doff, srcL + soff);
    }
}

__global__ __launch_bounds__(256) void gemm_qkv_mma(
    const float* __restrict__ bq, const float* __restrict__ bkv)
{
    extern __shared__ __align__(16) char smem[];
    uint32_t sb = (uint32_t)__cvta_generic_to_shared(smem);

    int b  = blockIdx.z;
    int n0 = blockIdx.x * 128;
    int s0 = blockIdx.y * 128;
    const __nv_bfloat16* xh_b = g_xh + (size_t)b * C_ * SEQ_;
    const __nv_bfloat16* xl_b = g_xl + (size_t)b * C_ * SEQ_;

    int tid = threadIdx.x, warp = tid >> 5, lane = tid & 31;
    int g = lane >> 2, tg = lane & 3;
    int wm = (warp & 1) * 64, wn = (warp >> 1) * 32;

    float acc[4][4][4];
    #pragma unroll
    for (int i = 0; i < 4; i++)
        #pragma unroll
        for (int j = 0; j < 4; j++)
            #pragma unroll
            for (int q = 0; q < 4; q++) acc[i][j][q] = 0.f;

    // prologue: stage 0, 1
    fill_trans_pair(sb,         xh_b, xl_b, SEQ_, s0, 0, tid);
    fill_trans_pair(sb + 16384, g_wh, g_wl, NQKV, n0, 0, tid);
    CP_COMMIT();
    fill_trans_pair(sb + 32768,         xh_b, xl_b, SEQ_, s0, 32, tid);
    fill_trans_pair(sb + 32768 + 16384, g_wh, g_wl, NQKV, n0, 32, tid);
    CP_COMMIT();

    for (int kt = 0; kt < NKT; kt++) {
        CP_WAIT1();
        __syncthreads();
        uint32_t sA = sb + (kt & 1) * 32768;
        uint32_t sB = sA + 16384;

        #pragma unroll
        for (int ks = 0; ks < 2; ks++) {
            int row  = ks * 16 + (lane & 7) + ((lane >> 4) << 3);
            int chs  = (lane >> 3) & 1;
            int rx   = row & 7;
            uint32_t rowoff = row * 256;

            uint32_t ah[4][4], al[4][4];
            #pragma unroll
            for (int mt = 0; mt < 4; mt++) {
                int ch = ((wm + mt * 16) >> 3) + chs;
                uint32_t off = rowoff + ((ch ^ rx) << 4);
                ldsm4t(ah[mt], sA + off);
                ldsm4t(al[mt], sA + 8192 + off);
            }
            uint32_t bh[4][2], bl[4][2];
            #pragma unroll
            for (int p = 0; p < 2; p++) {
                int ch = ((wn + p * 16) >> 3) + chs;
                uint32_t off = rowoff + ((ch ^ rx) << 4);
                uint32_t r[4], rl[4];
                ldsm4t(r,  sB + off);
                ldsm4t(rl, sB + 8192 + off);
                bh[2*p][0] = r[0];  bh[2*p][1] = r[2];
                bh[2*p+1][0] = r[1]; bh[2*p+1][1] = r[3];
                bl[2*p][0] = rl[0]; bl[2*p][1] = rl[2];
                bl[2*p+1][0] = rl[1]; bl[2*p+1][1] = rl[3];
            }
            #pragma unroll
            for (int mt = 0; mt < 4; mt++)
                #pragma unroll
                for (int nt = 0; nt < 4; nt++) {
                    mma_bf16(acc[mt][nt], ah[mt], bh[nt]);
                    mma_bf16(acc[mt][nt], ah[mt], bl[nt]);
                    mma_bf16(acc[mt][nt], al[mt], bh[nt]);
                }
        }
        __syncthreads();
        if (kt + 2 < NKT) {
            uint32_t st = sb + (kt & 1) * 32768;
            int k0 = (kt + 2) * 32;
            fill_trans_pair(st,         xh_b, xl_b, SEQ_, s0, k0, tid);
            fill_trans_pair(st + 16384, g_wh, g_wl, NQKV, n0, k0, tid);
        }
        CP_COMMIT();
    }

    #pragma unroll
    for (int nt = 0; nt < 4; nt++) {
        int nglob = n0 + wn + nt * 8 + 2 * tg;
        float b0 = (nglob < 256) ? bq[nglob]     : bkv[nglob - 256];
        float b1 = (nglob < 256) ? bq[nglob + 1] : bkv[nglob - 255];
        #pragma unroll
        for (int mt = 0; mt < 4; mt++) {
            int s = s0 + wm + mt * 16 + g;
            size_t r0 = ((size_t)b * SEQ_ + s) * NQKV + nglob;
            size_t r1 = r0 + (size_t)8 * NQKV;
            *(float2*)(g_qkv + r0) = make_float2(acc[mt][nt][0] + b0,
                                                 acc[mt][nt][1] + b1);
            *(float2*)(g_qkv + r1) = make_float2(acc[mt][nt][2] + b0,
                                                 acc[mt][nt][3] + b1);
        }
    }
}

// ============================================================================
// Attention: per token, 4x4 over heads. One warp per token. Writes split bf16.
// ============================================================================
__global__ __launch_bounds__(256) void attn_kernel()
{
    int warp = threadIdx.x >> 5, l = threadIdx.x & 31;
    int t = blockIdx.x * 8 + warp;
    const float* base = g_qkv + (size_t)t * NQKV;

    float q0[4], q1[4], k0v[4], k1v[4];
    #pragma unroll
    for (int n = 0; n < 4; n++) {
        q0[n]  = base[n * 64 + l];
        q1[n]  = base[n * 64 + 32 + l];
        k0v[n] = base[256 + n * 64 + l];
        k1v[n] = base[256 + n * 64 + 32 + l];
    }
    float s[16];
    #pragma unroll
    for (int n = 0; n < 4; n++)
        #pragma unroll
        for (int m = 0; m < 4; m++)
            s[n * 4 + m] = q0[n] * k0v[m] + q1[n] * k1v[m];
    #pragma unroll
    for (int off = 16; off > 0; off >>= 1)
        #pragma unroll
        for (int i = 0; i < 16; i++)
            s[i] += __shfl_xor_sync(0xffffffffu, s[i], off);

    float w[16];
    #pragma unroll
    for (int n = 0; n < 4; n++) {
        float p0 = s[n*4+0] * 0.125f, p1 = s[n*4+1] * 0.125f;
        float p2 = s[n*4+2] * 0.125f, p3 = s[n*4+3] * 0.125f;
        float mx = fmaxf(fmaxf(p0, p1), fmaxf(p2, p3));
        float e0 = __expf(p0 - mx), e1 = __expf(p1 - mx);
        float e2 = __expf(p2 - mx), e3 = __expf(p3 - mx);
        float inv = 1.0f / (e0 + e1 + e2 + e3);
        w[n*4+0] = e0 * inv; w[n*4+1] = e1 * inv;
        w[n*4+2] = e2 * inv; w[n*4+3] = e3 * inv;
    }
    float o0[4] = {0.f,0.f,0.f,0.f}, o1[4] = {0.f,0.f,0.f,0.f};
    #pragma unroll
    for (int m = 0; m < 4; m++) {
        float v0 = base[512 + m * 64 + l];
        float v1 = base[512 + m * 64 + 32 + l];
        #pragma unroll
        for (int n = 0; n < 4; n++) {
            o0[n] += w[n * 4 + m] * v0;
            o1[n] += w[n * 4 + m] * v1;
        }
    }
    size_t d = (size_t)t * C_;
    #pragma unroll
    for (int n = 0; n < 4; n++) {
        __nv_bfloat16 h0 = __float2bfloat16(o0[n]);
        __nv_bfloat16 h1 = __float2bfloat16(o1[n]);
        g_ah[d + n * 64 + l]      = h0;
        g_ah[d + n * 64 + 32 + l] = h1;
        g_al[d + n * 64 + l]      = __float2bfloat16(o0[n] - __bfloat162float(h0));
        g_al[d + n * 64 + 32 + l] = __float2bfloat16(o1[n] - __bfloat162float(h1));
    }
}

// ============================================================================
// GEMM2 (+fused transpose): out[b,n,s] = sum_k attn[b,s,k]*wo[k,n] + bo[n]
//   A = attn (stored [s][k]) -> row-major tile, ldmatrix non-trans
//   B = wo  (stored [k][n])  -> trans tile
// ============================================================================
__global__ __launch_bounds__(256) void gemm_out_mma(
    const float* __restrict__ bo, float* __restrict__ out)
{
    extern __shared__ __align__(16) char smem[];
    uint32_t sb = (uint32_t)__cvta_generic_to_shared(smem);

    int b  = blockIdx.z;
    int n0 = blockIdx.x * 128;
    int s0 = blockIdx.y * 128;
    const __nv_bfloat16* ah_b = g_ah + (size_t)b * SEQ_ * C_;
    const __nv_bfloat16* al_b = g_al + (size_t)b * SEQ_ * C_;

    int tid = threadIdx.x, warp = tid >> 5, lane = tid & 31;
    int g = lane >> 2, tg = lane & 3;
    int wm = (warp & 1) * 64, wn = (warp >> 1) * 32;

    float acc[4][4][4];
    #pragma unroll
    for (int i = 0; i < 4; i++)
        #pragma unroll
        for (int j = 0; j < 4; j++)
            #pragma unroll
            for (int q = 0; q < 4; q++) acc[i][j][q] = 0.f;

    // A fill: 128 rows(s) x 32 k, 64B rows, 4 chunks, swizzle chunk^((row>>1)&3)
    auto fillA = [&](uint32_t st, int k0) {
        #pragma unroll
        for (int i = 0; i < 2; i++) {
            int idx2 = (i << 8) + tid;
            int row = idx2 >> 2, chunk = idx2 & 3;
            uint32_t doff = row * 64 + ((chunk ^ ((row >> 1) & 3)) << 4);
            size_t soff = (size_t)(s0 + row) * C_ + k0 + chunk * 8;
            cpa16(st + doff,        ah_b + soff);
            cpa16(st + 8192 + doff, al_b + soff);
        }
    };
    auto fillB = [&](uint32_t st, int k0) {
        fill_trans_pair(st, g_woh, g_wol, C_, n0, k0, tid);
    };

    fillA(sb, 0);          fillB(sb + 16384, 0);          CP_COMMIT();
    fillA(sb + 32768, 32); fillB(sb + 32768 + 16384, 32); CP_COMMIT();

    for (int kt = 0; kt < NKT; kt++) {
        CP_WAIT1();
        __syncthreads();
        uint32_t sA = sb + (kt & 1) * 32768;
        uint32_t sB = sA + 16384;

        #pragma unroll
        for (int ks = 0; ks < 2; ks++) {
            // A non-trans fragments
            uint32_t ah[4][4], al[4][4];
            #pragma unroll
            for (int mt = 0; mt < 4; mt++) {
                int row = wm + mt * 16 + (lane & 15);
                int ch  = ks * 2 + (lane >> 4);
                uint32_t off = row * 64 + ((ch ^ ((row >> 1) & 3)) << 4);
                ldsm4(ah[mt], sA + off);
                ldsm4(al[mt], sA + 8192 + off);
            }
            // B trans fragments
            int rowb = ks * 16 + (lane & 7) + ((lane >> 4) << 3);
            int chs  = (lane >> 3) & 1;
            int rx   = rowb & 7;
            uint32_t rowoff = rowb * 256;
            uint32_t bh[4][2], bl[4][2];
            #pragma unroll
            for (int p = 0; p < 2; p++) {
                int ch = ((wn + p * 16) >> 3) + chs;
                uint32_t off = rowoff + ((ch ^ rx) << 4);
                uint32_t r[4], rl[4];
                ldsm4t(r,  sB + off);
                ldsm4t(rl, sB + 8192 + off);
                bh[2*p][0] = r[0];  bh[2*p][1] = r[2];
                bh[2*p+1][0] = r[1]; bh[2*p+1][1] = r[3];
                bl[2*p][0] = rl[0]; bl[2*p][1] = rl[2];
                bl[2*p+1][0] = rl[1]; bl[2*p+1][1] = rl[3];
            }
            #pragma unroll
            for (int mt = 0; mt < 4; mt++)
                #pragma unroll
                for (int nt = 0; nt < 4; nt++) {
                    mma_bf16(acc[mt][nt], ah[mt], bh[nt]);
                    mma_bf16(acc[mt][nt], ah[mt], bl[nt]);
                    mma_bf16(acc[mt][nt], al[mt], bh[nt]);
                }
        }
        __syncthreads();
        if (kt + 2 < NKT) {
            uint32_t st = sb + (kt & 1) * 32768;
            int k0 = (kt + 2) * 32;
            fillA(st, k0); fillB(st + 16384, k0);
        }
        CP_COMMIT();
    }

    // fused-transpose epilogue
    float* ob = out + (size_t)b * C_ * SEQ_;
    #pragma unroll
    for (int nt = 0; nt < 4; nt++) {
        int c = n0 + wn + nt * 8 + 2 * tg;
        float b0 = bo[c], b1 = bo[c + 1];
        #pragma unroll
        for (int mt = 0; mt < 4; mt++) {
            int s = s0 + wm + mt * 16 + g;
            ob[(size_t)c       * SEQ_ + s]     = acc[mt][nt][0] + b0;
            ob[(size_t)(c + 1) * SEQ_ + s]     = acc[mt][nt][1] + b1;
            ob[(size_t)c       * SEQ_ + s + 8] = acc[mt][nt][2] + b0;
            ob[(size_t)(c + 1) * SEQ_ + s + 8] = acc[mt][nt][3] + b1;
        }
    }
}

// ============================================================================
extern "C" void kernel_launch(void* const* d_in, const int* in_sizes, int n_in,
                              void* d_out, int out_size)
{
    const float* x   = (const float*)d_in[0];
    const float* wq  = (const float*)d_in[1];
    const float* bq  = (const float*)d_in[2];
    const float* wkv = (const float*)d_in[3];
    const float* bkv = (const float*)d_in[4];
    const float* wo  = (const float*)d_in[5];
    const float* bo  = (const float*)d_in[6];
    float* out = (float*)d_out;

    static bool attr_set = false;
    if (!attr_set) {
        cudaFuncSetAttribute(gemm_qkv_mma,
            cudaFuncAttributeMaxDynamicSharedMemorySize, 65536);
        cudaFuncSetAttribute(gemm_out_mma,
            cudaFuncAttributeMaxDynamicSharedMemorySize, 65536);
        attr_set = true;
    }

    __nv_bfloat16 *xh, *xl, *woh, *wol;
    cudaGetSymbolAddress((void**)&xh,  g_xh);
    cudaGetSymbolAddress((void**)&xl,  g_xl);
    cudaGetSymbolAddress((void**)&woh, g_woh);
    cudaGetSymbolAddress((void**)&wol, g_wol);

    // split passes
    int nx4 = (B_ * C_ * SEQ_) / 4;
    split_f4<<<(nx4 + 255) / 256, 256>>>((const float4*)x,
                                         (uint2*)xh, (uint2*)xl, nx4);
    int nw4 = (C_ * C_) / 4;
    split_f4<<<(nw4 + 255) / 256, 256>>>((const float4*)wo,
                                         (uint2*)woh, (uint2*)wol, nw4);
    split_wqkv<<<(C_ * NQKV) / 256, 256>>>(wq, wkv);

    gemm_qkv_mma<<<dim3(6, 32, 16), 256, 65536>>>(bq, bkv);
    attn_kernel<<<(B_ * SEQ_) / 8, 256>>>();
    gemm_out_mma<<<dim3(2, 32, 16), 256, 65536>>>(bo, out);
}

// round 5
// speedup vs baseline: 2.8301x; 1.2194x over previous
#include <cuda_runtime.h>
#include <cuda_fp16.h>
#include <cstdint>

#define B_   16
#define C_   256
#define SEQ_ 4096
#define NQKV 768
#define NKT  8          // K=256 / BK=32

// ---------------- scratch (static device globals) ---------------------------
__device__ __half g_xh [(size_t)B_ * C_ * SEQ_];   // x fp16 [b][k][s]
__device__ __half g_wh [(size_t)C_ * NQKV];        // Wqkv hi [k][768]
__device__ __half g_wl [(size_t)C_ * NQKV];        // Wqkv lo
__device__ __half g_woh[(size_t)C_ * C_];          // Wo hi [k][n]
__device__ __half g_wol[(size_t)C_ * C_];          // Wo lo
__device__ float  g_qkv[(size_t)B_ * SEQ_ * NQKV]; // [b][s][768]
__device__ __half g_ah [(size_t)B_ * SEQ_ * C_];   // attn out hi [b][s][k]
__device__ __half g_al [(size_t)B_ * SEQ_ * C_];   // attn out lo

// ---------------- PTX helpers ------------------------------------------------
__device__ __forceinline__ void mma_f16(float* acc, const uint32_t* a,
                                        const uint32_t* b) {
    asm volatile(
        "mma.sync.aligned.m16n8k16.row.col.f32.f16.f16.f32 "
        "{%0,%1,%2,%3}, {%4,%5,%6,%7}, {%8,%9}, {%0,%1,%2,%3};"
        : "+f"(acc[0]), "+f"(acc[1]), "+f"(acc[2]), "+f"(acc[3])
        : "r"(a[0]), "r"(a[1]), "r"(a[2]), "r"(a[3]), "r"(b[0]), "r"(b[1]));
}
__device__ __forceinline__ void ldsm4(uint32_t* r, uint32_t addr) {
    asm volatile("ldmatrix.sync.aligned.m8n8.x4.shared.b16 {%0,%1,%2,%3}, [%4];"
        : "=r"(r[0]), "=r"(r[1]), "=r"(r[2]), "=r"(r[3]) : "r"(addr));
}
__device__ __forceinline__ void ldsm4t(uint32_t* r, uint32_t addr) {
    asm volatile("ldmatrix.sync.aligned.m8n8.x4.trans.shared.b16 {%0,%1,%2,%3}, [%4];"
        : "=r"(r[0]), "=r"(r[1]), "=r"(r[2]), "=r"(r[3]) : "r"(addr));
}
__device__ __forceinline__ void cpa16(uint32_t dst, const void* src) {
    asm volatile("cp.async.cg.shared.global [%0], [%1], 16;" :: "r"(dst), "l"(src));
}
#define CP_COMMIT()  asm volatile("cp.async.commit_group;")
#define CP_WAIT1()   asm volatile("cp.async.wait_group 1;")

// ============================================================================
// Conversion passes
// ============================================================================
__global__ void conv_x(const float4* __restrict__ in, uint2* __restrict__ oh,
                       int n4)
{
    int i = blockIdx.x * 256 + threadIdx.x;
    if (i >= n4) return;
    float4 v = in[i];
    __half2 h01 = __floats2half2_rn(v.x, v.y);
    __half2 h23 = __floats2half2_rn(v.z, v.w);
    uint2 o;
    o.x = *(uint32_t*)&h01; o.y = *(uint32_t*)&h23;
    oh[i] = o;
}

__global__ void split_wo4(const float4* __restrict__ in,
                          uint2* __restrict__ oh, uint2* __restrict__ ol, int n4)
{
    int i = blockIdx.x * 256 + threadIdx.x;
    if (i >= n4) return;
    float4 v = in[i];
    __half2 h01 = __floats2half2_rn(v.x, v.y);
    __half2 h23 = __floats2half2_rn(v.z, v.w);
    float2 hf01 = __half22float2(h01), hf23 = __half22float2(h23);
    __half2 l01 = __floats2half2_rn(v.x - hf01.x, v.y - hf01.y);
    __half2 l23 = __floats2half2_rn(v.z - hf23.x, v.w - hf23.y);
    uint2 ho, lo;
    ho.x = *(uint32_t*)&h01; ho.y = *(uint32_t*)&h23;
    lo.x = *(uint32_t*)&l01; lo.y = *(uint32_t*)&l23;
    oh[i] = ho; ol[i] = lo;
}

__global__ void split_wqkv(const float* __restrict__ wq,
                           const float* __restrict__ wkv)
{
    int idx = blockIdx.x * 256 + threadIdx.x;      // 256*768
    int k = idx / NQKV, n = idx % NQKV;
    float f = (n < 256) ? wq[k * 256 + n] : wkv[k * 512 + (n - 256)];
    __half h = __float2half_rn(f);
    g_wh[idx] = h;
    g_wl[idx] = __float2half_rn(f - __half2float(h));
}

// ============================================================================
// GEMM1 (fp16, 2-term): qkv[b,s,n] = sum_k x[b,k,s]*W[k,n] + bias[n]
//   A = x fp16 (stored [k][s]) -> trans tile, ldmatrix.trans (hi only)
//   B = W hi/lo (stored [k][n]) -> trans tiles
//   128x128 block, BK=32, 8 warps (2x4), D = Ah*Bh + Ah*Bl.
//   smem/stage: A 8KB @0, Bh 8KB @8192, Bl 8KB @16384. 2 stages (48KB).
// ============================================================================
__global__ __launch_bounds__(256) void gemm_qkv_mma(
    const float* __restrict__ bq, const float* __restrict__ bkv)
{
    extern __shared__ __align__(16) char smem[];
    uint32_t sb = (uint32_t)__cvta_generic_to_shared(smem);

    int b  = blockIdx.z;
    int n0 = blockIdx.x * 128;
    int s0 = blockIdx.y * 128;
    const __half* xb = g_xh + (size_t)b * C_ * SEQ_;

    int tid = threadIdx.x, warp = tid >> 5, lane = tid & 31;
    int g = lane >> 2, tg = lane & 3;
    int wm = (warp & 1) * 64, wn = (warp >> 1) * 32;

    float acc[4][4][4];
    #pragma unroll
    for (int i = 0; i < 4; i++)
        #pragma unroll
        for (int j = 0; j < 4; j++)
            #pragma unroll
            for (int q = 0; q < 4; q++) acc[i][j][q] = 0.f;

    // tile fill: 32 rows(k) x 128 cols, 256B rows, 16 chunks, swizzle ch^(row&7)
    auto fill = [&](uint32_t st, int k0) {
        #pragma unroll
        for (int i = 0; i < 2; i++) {
            int idx2 = (i << 8) + tid;
            int row = idx2 >> 4, chunk = idx2 & 15;
            uint32_t doff = row * 256 + ((chunk ^ (row & 7)) << 4);
            cpa16(st + doff, xb + (size_t)(k0 + row) * SEQ_ + s0 + chunk * 8);
            size_t wo_off = (size_t)(k0 + row) * NQKV + n0 + chunk * 8;
            cpa16(st + 8192  + doff, g_wh + wo_off);
            cpa16(st + 16384 + doff, g_wl + wo_off);
        }
    };

    fill(sb, 0);          CP_COMMIT();
    fill(sb + 24576, 32); CP_COMMIT();

    for (int kt = 0; kt < NKT; kt++) {
        CP_WAIT1();
        __syncthreads();
        uint32_t sA = sb + (kt & 1) * 24576;

        #pragma unroll
        for (int ks = 0; ks < 2; ks++) {
            int row = ks * 16 + (lane & 7) + ((lane >> 4) << 3);
            int chs = (lane >> 3) & 1;
            int rx  = row & 7;
            uint32_t rowoff = row * 256;

            uint32_t ah[4][4];
            #pragma unroll
            for (int mt = 0; mt < 4; mt++) {
                int ch = ((wm + mt * 16) >> 3) + chs;
                ldsm4t(ah[mt], sA + rowoff + ((ch ^ rx) << 4));
            }
            uint32_t bh[4][2], bl[4][2];
            #pragma unroll
            for (int p = 0; p < 2; p++) {
                int ch = ((wn + p * 16) >> 3) + chs;
                uint32_t off = rowoff + ((ch ^ rx) << 4);
                uint32_t r[4], rl[4];
                ldsm4t(r,  sA + 8192  + off);
                ldsm4t(rl, sA + 16384 + off);
                bh[2*p][0] = r[0];   bh[2*p][1] = r[2];
                bh[2*p+1][0] = r[1]; bh[2*p+1][1] = r[3];
                bl[2*p][0] = rl[0];  bl[2*p][1] = rl[2];
                bl[2*p+1][0] = rl[1]; bl[2*p+1][1] = rl[3];
            }
            #pragma unroll
            for (int mt = 0; mt < 4; mt++)
                #pragma unroll
                for (int nt = 0; nt < 4; nt++) {
                    mma_f16(acc[mt][nt], ah[mt], bh[nt]);
                    mma_f16(acc[mt][nt], ah[mt], bl[nt]);
                }
        }
        __syncthreads();
        if (kt + 2 < NKT)
            fill(sb + (kt & 1) * 24576, (kt + 2) * 32);
        CP_COMMIT();
    }

    #pragma unroll
    for (int nt = 0; nt < 4; nt++) {
        int nglob = n0 + wn + nt * 8 + 2 * tg;
        float b0 = (nglob < 256) ? bq[nglob]     : bkv[nglob - 256];
        float b1 = (nglob < 256) ? bq[nglob + 1] : bkv[nglob - 255];
        #pragma unroll
        for (int mt = 0; mt < 4; mt++) {
            int s = s0 + wm + mt * 16 + g;
            size_t r0 = ((size_t)b * SEQ_ + s) * NQKV + nglob;
            size_t r1 = r0 + (size_t)8 * NQKV;
            *(float2*)(g_qkv + r0) = make_float2(acc[mt][nt][0] + b0,
                                                 acc[mt][nt][1] + b1);
            *(float2*)(g_qkv + r1) = make_float2(acc[mt][nt][2] + b0,
                                                 acc[mt][nt][3] + b1);
        }
    }
}

// ============================================================================
// Attention: per token, 4x4 over heads. One warp per token. Writes fp16 hi/lo.
// ============================================================================
__global__ __launch_bounds__(256) void attn_kernel()
{
    int warp = threadIdx.x >> 5, l = threadIdx.x & 31;
    int t = blockIdx.x * 8 + warp;
    const float* base = g_qkv + (size_t)t * NQKV;

    float q0[4], q1[4], k0v[4], k1v[4];
    #pragma unroll
    for (int n = 0; n < 4; n++) {
        q0[n]  = base[n * 64 + l];
        q1[n]  = base[n * 64 + 32 + l];
        k0v[n] = base[256 + n * 64 + l];
        k1v[n] = base[256 + n * 64 + 32 + l];
    }
    float s[16];
    #pragma unroll
    for (int n = 0; n < 4; n++)
        #pragma unroll
        for (int m = 0; m < 4; m++)
            s[n * 4 + m] = q0[n] * k0v[m] + q1[n] * k1v[m];
    #pragma unroll
    for (int off = 16; off > 0; off >>= 1)
        #pragma unroll
        for (int i = 0; i < 16; i++)
            s[i] += __shfl_xor_sync(0xffffffffu, s[i], off);

    float w[16];
    #pragma unroll
    for (int n = 0; n < 4; n++) {
        float p0 = s[n*4+0] * 0.125f, p1 = s[n*4+1] * 0.125f;
        float p2 = s[n*4+2] * 0.125f, p3 = s[n*4+3] * 0.125f;
        float mx = fmaxf(fmaxf(p0, p1), fmaxf(p2, p3));
        float e0 = __expf(p0 - mx), e1 = __expf(p1 - mx);
        float e2 = __expf(p2 - mx), e3 = __expf(p3 - mx);
        float inv = 1.0f / (e0 + e1 + e2 + e3);
        w[n*4+0] = e0 * inv; w[n*4+1] = e1 * inv;
        w[n*4+2] = e2 * inv; w[n*4+3] = e3 * inv;
    }
    float o0[4] = {0.f,0.f,0.f,0.f}, o1[4] = {0.f,0.f,0.f,0.f};
    #pragma unroll
    for (int m = 0; m < 4; m++) {
        float v0 = base[512 + m * 64 + l];
        float v1 = base[512 + m * 64 + 32 + l];
        #pragma unroll
        for (int n = 0; n < 4; n++) {
            o0[n] += w[n * 4 + m] * v0;
            o1[n] += w[n * 4 + m] * v1;
        }
    }
    size_t d = (size_t)t * C_;
    #pragma unroll
    for (int n = 0; n < 4; n++) {
        __half h0 = __float2half_rn(o0[n]);
        __half h1 = __float2half_rn(o1[n]);
        g_ah[d + n * 64 + l]      = h0;
        g_ah[d + n * 64 + 32 + l] = h1;
        g_al[d + n * 64 + l]      = __float2half_rn(o0[n] - __half2float(h0));
        g_al[d + n * 64 + 32 + l] = __float2half_rn(o1[n] - __half2float(h1));
    }
}

// ============================================================================
// GEMM2 (fp16, 3-term, fused transpose): out[b,n,s] = sum_k attn[b,s,k]*wo[k,n]+bo[n]
//   A = attn hi/lo (stored [s][k]) -> row-major tile, ldmatrix non-trans
//   B = wo hi/lo (stored [k][n])   -> trans tile
//   smem/stage: Ah@0, Al@8192, Bh@16384, Bl@24576. 2 stages (64KB).
// ============================================================================
__global__ __launch_bounds__(256) void gemm_out_mma(
    const float* __restrict__ bo, float* __restrict__ out)
{
    extern __shared__ __align__(16) char smem[];
    uint32_t sb = (uint32_t)__cvta_generic_to_shared(smem);

    int b  = blockIdx.z;
    int n0 = blockIdx.x * 128;
    int s0 = blockIdx.y * 128;
    const __half* ah_b = g_ah + (size_t)b * SEQ_ * C_;
    const __half* al_b = g_al + (size_t)b * SEQ_ * C_;

    int tid = threadIdx.x, warp = tid >> 5, lane = tid & 31;
    int g = lane >> 2, tg = lane & 3;
    int wm = (warp & 1) * 64, wn = (warp >> 1) * 32;

    float acc[4][4][4];
    #pragma unroll
    for (int i = 0; i < 4; i++)
        #pragma unroll
        for (int j = 0; j < 4; j++)
            #pragma unroll
            for (int q = 0; q < 4; q++) acc[i][j][q] = 0.f;

    auto fill = [&](uint32_t st, int k0) {
        #pragma unroll
        for (int i = 0; i < 2; i++) {
            int idx2 = (i << 8) + tid;
            // A: 128 rows(s) x 32 k, 64B rows, 4 chunks, swizzle ch^((row>>1)&3)
            int rowA = idx2 >> 2, chA = idx2 & 3;
            uint32_t dA = rowA * 64 + ((chA ^ ((rowA >> 1) & 3)) << 4);
            size_t sA_off = (size_t)(s0 + rowA) * C_ + k0 + chA * 8;
            cpa16(st + dA,        ah_b + sA_off);
            cpa16(st + 8192 + dA, al_b + sA_off);
            // B: 32 rows(k) x 128 cols(n), 256B rows, swizzle ch^(row&7)
            int rowB = idx2 >> 4, chB = idx2 & 15;
            uint32_t dB = rowB * 256 + ((chB ^ (rowB & 7)) << 4);
            size_t sB_off = (size_t)(k0 + rowB) * C_ + n0 + chB * 8;
            cpa16(st + 16384 + dB, g_woh + sB_off);
            cpa16(st + 24576 + dB, g_wol + sB_off);
        }
    };

    fill(sb, 0);          CP_COMMIT();
    fill(sb + 32768, 32); CP_COMMIT();

    for (int kt = 0; kt < NKT; kt++) {
        CP_WAIT1();
        __syncthreads();
        uint32_t sA = sb + (kt & 1) * 32768;
        uint32_t sB = sA + 16384;

        #pragma unroll
        for (int ks = 0; ks < 2; ks++) {
            uint32_t ah[4][4], al[4][4];
            #pragma unroll
            for (int mt = 0; mt < 4; mt++) {
                int row = wm + mt * 16 + (lane & 15);
                int ch  = ks * 2 + (lane >> 4);
                uint32_t off = row * 64 + ((ch ^ ((row >> 1) & 3)) << 4);
                ldsm4(ah[mt], sA + off);
                ldsm4(al[mt], sA + 8192 + off);
            }
            int rowb = ks * 16 + (lane & 7) + ((lane >> 4) << 3);
            int chs  = (lane >> 3) & 1;
            int rx   = rowb & 7;
            uint32_t rowoff = rowb * 256;
            uint32_t bh[4][2], bl[4][2];
            #pragma unroll
            for (int p = 0; p < 2; p++) {
                int ch = ((wn + p * 16) >> 3) + chs;
                uint32_t off = rowoff + ((ch ^ rx) << 4);
                uint32_t r[4], rl[4];
                ldsm4t(r,  sB + off);
                ldsm4t(rl, sB + 8192 + off);
                bh[2*p][0] = r[0];   bh[2*p][1] = r[2];
                bh[2*p+1][0] = r[1]; bh[2*p+1][1] = r[3];
                bl[2*p][0] = rl[0];  bl[2*p][1] = rl[2];
                bl[2*p+1][0] = rl[1]; bl[2*p+1][1] = rl[3];
            }
            #pragma unroll
            for (int mt = 0; mt < 4; mt++)
                #pragma unroll
                for (int nt = 0; nt < 4; nt++) {
                    mma_f16(acc[mt][nt], ah[mt], bh[nt]);
                    mma_f16(acc[mt][nt], ah[mt], bl[nt]);
                    mma_f16(acc[mt][nt], al[mt], bh[nt]);
                }
        }
        __syncthreads();
        if (kt + 2 < NKT)
            fill(sb + (kt & 1) * 32768, (kt + 2) * 32);
        CP_COMMIT();
    }

    // fused-transpose epilogue
    float* ob = out + (size_t)b * C_ * SEQ_;
    #pragma unroll
    for (int nt = 0; nt < 4; nt++) {
        int c = n0 + wn + nt * 8 + 2 * tg;
        float b0 = bo[c], b1 = bo[c + 1];
        #pragma unroll
        for (int mt = 0; mt < 4; mt++) {
            int s = s0 + wm + mt * 16 + g;
            ob[(size_t)c       * SEQ_ + s]     = acc[mt][nt][0] + b0;
            ob[(size_t)(c + 1) * SEQ_ + s]     = acc[mt][nt][1] + b1;
            ob[(size_t)c       * SEQ_ + s + 8] = acc[mt][nt][2] + b0;
            ob[(size_t)(c + 1) * SEQ_ + s + 8] = acc[mt][nt][3] + b1;
        }
    }
}

// ============================================================================
extern "C" void kernel_launch(void* const* d_in, const int* in_sizes, int n_in,
                              void* d_out, int out_size)
{
    const float* x   = (const float*)d_in[0];
    const float* wq  = (const float*)d_in[1];
    const float* bq  = (const float*)d_in[2];
    const float* wkv = (const float*)d_in[3];
    const float* bkv = (const float*)d_in[4];
    const float* wo  = (const float*)d_in[5];
    const float* bo  = (const float*)d_in[6];
    float* out = (float*)d_out;

    static bool attr_set = false;
    if (!attr_set) {
        cudaFuncSetAttribute(gemm_qkv_mma,
            cudaFuncAttributeMaxDynamicSharedMemorySize, 49152);
        cudaFuncSetAttribute(gemm_out_mma,
            cudaFuncAttributeMaxDynamicSharedMemorySize, 65536);
        attr_set = true;
    }

    __half *xh, *woh, *wol;
    cudaGetSymbolAddress((void**)&xh,  g_xh);
    cudaGetSymbolAddress((void**)&woh, g_woh);
    cudaGetSymbolAddress((void**)&wol, g_wol);

    int nx4 = (B_ * C_ * SEQ_) / 4;
    conv_x<<<(nx4 + 255) / 256, 256>>>((const float4*)x, (uint2*)xh, nx4);
    int nw4 = (C_ * C_) / 4;
    split_wo4<<<(nw4 + 255) / 256, 256>>>((const float4*)wo,
                                          (uint2*)woh, (uint2*)wol, nw4);
    split_wqkv<<<(C_ * NQKV) / 256, 256>>>(wq, wkv);

    gemm_qkv_mma<<<dim3(6, 32, 16), 256, 49152>>>(bq, bkv);
    attn_kernel<<<(B_ * SEQ_) / 8, 256>>>();
    gemm_out_mma<<<dim3(2, 32, 16), 256, 65536>>>(bo, out);
}

// round 6
// speedup vs baseline: 3.9000x; 1.3780x over previous
#include <cuda_runtime.h>
#include <cuda_fp16.h>
#include <cstdint>

#define B_   16
#define C_   256
#define SEQ_ 4096
#define NQKV 768

// ---------------- scratch (static device globals) ---------------------------
__device__ __half g_xh [(size_t)B_ * C_ * SEQ_];   // x fp16 [b][k][s]
__device__ __half g_wh [(size_t)C_ * NQKV];        // Wqkv fp16 [k][768]
__device__ __half g_woh[(size_t)C_ * C_];          // Wo hi [k][n]
__device__ __half g_wol[(size_t)C_ * C_];          // Wo lo
__device__ __half g_qkv[(size_t)B_ * SEQ_ * NQKV]; // fp16 [b][s][768]
__device__ __half g_ah [(size_t)B_ * SEQ_ * C_];   // attn out fp16 [b][s][k]

// ---------------- PTX helpers ------------------------------------------------
__device__ __forceinline__ void mma_f16(float* acc, const uint32_t* a,
                                        const uint32_t* b) {
    asm volatile(
        "mma.sync.aligned.m16n8k16.row.col.f32.f16.f16.f32 "
        "{%0,%1,%2,%3}, {%4,%5,%6,%7}, {%8,%9}, {%0,%1,%2,%3};"
        : "+f"(acc[0]), "+f"(acc[1]), "+f"(acc[2]), "+f"(acc[3])
        : "r"(a[0]), "r"(a[1]), "r"(a[2]), "r"(a[3]), "r"(b[0]), "r"(b[1]));
}
__device__ __forceinline__ void ldsm4(uint32_t* r, uint32_t addr) {
    asm volatile("ldmatrix.sync.aligned.m8n8.x4.shared.b16 {%0,%1,%2,%3}, [%4];"
        : "=r"(r[0]), "=r"(r[1]), "=r"(r[2]), "=r"(r[3]) : "r"(addr));
}
__device__ __forceinline__ void ldsm4t(uint32_t* r, uint32_t addr) {
    asm volatile("ldmatrix.sync.aligned.m8n8.x4.trans.shared.b16 {%0,%1,%2,%3}, [%4];"
        : "=r"(r[0]), "=r"(r[1]), "=r"(r[2]), "=r"(r[3]) : "r"(addr));
}
__device__ __forceinline__ void cpa16(uint32_t dst, const void* src) {
    asm volatile("cp.async.cg.shared.global [%0], [%1], 16;" :: "r"(dst), "l"(src));
}
#define CP_COMMIT()  asm volatile("cp.async.commit_group;")
#define CP_WAIT1()   asm volatile("cp.async.wait_group 1;")

// ============================================================================
// Conversion passes
// ============================================================================
__global__ void conv_x(const float4* __restrict__ in, uint2* __restrict__ oh,
                       int n4)
{
    int i = blockIdx.x * 256 + threadIdx.x;
    if (i >= n4) return;
    float4 v = in[i];
    __half2 h01 = __floats2half2_rn(v.x, v.y);
    __half2 h23 = __floats2half2_rn(v.z, v.w);
    uint2 o;
    o.x = *(uint32_t*)&h01; o.y = *(uint32_t*)&h23;
    oh[i] = o;
}

__global__ void split_wo4(const float4* __restrict__ in,
                          uint2* __restrict__ oh, uint2* __restrict__ ol, int n4)
{
    int i = blockIdx.x * 256 + threadIdx.x;
    if (i >= n4) return;
    float4 v = in[i];
    __half2 h01 = __floats2half2_rn(v.x, v.y);
    __half2 h23 = __floats2half2_rn(v.z, v.w);
    float2 hf01 = __half22float2(h01), hf23 = __half22float2(h23);
    __half2 l01 = __floats2half2_rn(v.x - hf01.x, v.y - hf01.y);
    __half2 l23 = __floats2half2_rn(v.z - hf23.x, v.w - hf23.y);
    uint2 ho, lo;
    ho.x = *(uint32_t*)&h01; ho.y = *(uint32_t*)&h23;
    lo.x = *(uint32_t*)&l01; lo.y = *(uint32_t*)&l23;
    oh[i] = ho; ol[i] = lo;
}

__global__ void conv_wqkv(const float* __restrict__ wq,
                          const float* __restrict__ wkv)
{
    int idx = blockIdx.x * 256 + threadIdx.x;      // 256*768
    int k = idx / NQKV, n = idx % NQKV;
    float f = (n < 256) ? wq[k * 256 + n] : wkv[k * 512 + (n - 256)];
    g_wh[idx] = __float2half_rn(f);
}

// ============================================================================
// GEMM1 (fp16, 1-term): qkv[b,s,n] = sum_k x[b,k,s]*W[k,n] + bias[n]
//   A = x fp16 [k][s] -> trans tile; B = W fp16 [k][n] -> trans tile.
//   128x128 block, BK=64, 8 warps (2x4). smem: A 16KB + B 16KB per stage, x2.
// ============================================================================
__global__ __launch_bounds__(256) void gemm_qkv_mma(
    const float* __restrict__ bq, const float* __restrict__ bkv)
{
    extern __shared__ __align__(16) char smem[];
    uint32_t sb = (uint32_t)__cvta_generic_to_shared(smem);

    int b  = blockIdx.z;
    int n0 = blockIdx.x * 128;
    int s0 = blockIdx.y * 128;
    const __half* xb = g_xh + (size_t)b * C_ * SEQ_;

    int tid = threadIdx.x, warp = tid >> 5, lane = tid & 31;
    int g = lane >> 2, tg = lane & 3;
    int wm = (warp & 1) * 64, wn = (warp >> 1) * 32;

    float acc[4][4][4];
    #pragma unroll
    for (int i = 0; i < 4; i++)
        #pragma unroll
        for (int j = 0; j < 4; j++)
            #pragma unroll
            for (int q = 0; q < 4; q++) acc[i][j][q] = 0.f;

    // tile fill: 64 rows(k) x 128 cols, 256B rows, 16 chunks, swizzle ch^(row&7)
    auto fill = [&](uint32_t st, int k0) {
        #pragma unroll
        for (int i = 0; i < 4; i++) {
            int idx2 = (i << 8) + tid;
            int row = idx2 >> 4, chunk = idx2 & 15;
            uint32_t doff = row * 256 + ((chunk ^ (row & 7)) << 4);
            cpa16(st + doff, xb + (size_t)(k0 + row) * SEQ_ + s0 + chunk * 8);
            cpa16(st + 16384 + doff,
                  g_wh + (size_t)(k0 + row) * NQKV + n0 + chunk * 8);
        }
    };

    fill(sb, 0);          CP_COMMIT();
    fill(sb + 32768, 64); CP_COMMIT();

    for (int kt = 0; kt < 4; kt++) {
        CP_WAIT1();
        __syncthreads();
        uint32_t sA = sb + (kt & 1) * 32768;

        #pragma unroll
        for (int ks = 0; ks < 4; ks++) {
            int row = ks * 16 + (lane & 7) + ((lane >> 4) << 3);
            int chs = (lane >> 3) & 1;
            int rx  = row & 7;
            uint32_t rowoff = row * 256;

            uint32_t ah[4][4];
            #pragma unroll
            for (int mt = 0; mt < 4; mt++) {
                int ch = ((wm + mt * 16) >> 3) + chs;
                ldsm4t(ah[mt], sA + rowoff + ((ch ^ rx) << 4));
            }
            uint32_t bh[4][2];
            #pragma unroll
            for (int p = 0; p < 2; p++) {
                int ch = ((wn + p * 16) >> 3) + chs;
                uint32_t r[4];
                ldsm4t(r, sA + 16384 + rowoff + ((ch ^ rx) << 4));
                bh[2*p][0] = r[0];   bh[2*p][1] = r[2];
                bh[2*p+1][0] = r[1]; bh[2*p+1][1] = r[3];
            }
            #pragma unroll
            for (int mt = 0; mt < 4; mt++)
                #pragma unroll
                for (int nt = 0; nt < 4; nt++)
                    mma_f16(acc[mt][nt], ah[mt], bh[nt]);
        }
        __syncthreads();
        if (kt < 2)
            fill(sb + (kt & 1) * 32768, (kt + 2) * 64);
        CP_COMMIT();
    }

    #pragma unroll
    for (int nt = 0; nt < 4; nt++) {
        int nglob = n0 + wn + nt * 8 + 2 * tg;
        float b0 = (nglob < 256) ? bq[nglob]     : bkv[nglob - 256];
        float b1 = (nglob < 256) ? bq[nglob + 1] : bkv[nglob - 255];
        #pragma unroll
        for (int mt = 0; mt < 4; mt++) {
            int s = s0 + wm + mt * 16 + g;
            size_t r0 = ((size_t)b * SEQ_ + s) * NQKV + nglob;
            size_t r1 = r0 + (size_t)8 * NQKV;
            *(__half2*)(g_qkv + r0) =
                __floats2half2_rn(acc[mt][nt][0] + b0, acc[mt][nt][1] + b1);
            *(__half2*)(g_qkv + r1) =
                __floats2half2_rn(acc[mt][nt][2] + b0, acc[mt][nt][3] + b1);
        }
    }
}

// ============================================================================
// Attention: per token, 4x4 over heads. One warp per token. fp16 in/out.
// ============================================================================
__global__ __launch_bounds__(256) void attn_kernel()
{
    int warp = threadIdx.x >> 5, l = threadIdx.x & 31;
    int t = blockIdx.x * 8 + warp;
    const __half* base = g_qkv + (size_t)t * NQKV;

    float q0[4], q1[4], k0v[4], k1v[4];
    #pragma unroll
    for (int n = 0; n < 4; n++) {
        q0[n]  = __half2float(base[n * 64 + l]);
        q1[n]  = __half2float(base[n * 64 + 32 + l]);
        k0v[n] = __half2float(base[256 + n * 64 + l]);
        k1v[n] = __half2float(base[256 + n * 64 + 32 + l]);
    }
    float s[16];
    #pragma unroll
    for (int n = 0; n < 4; n++)
        #pragma unroll
        for (int m = 0; m < 4; m++)
            s[n * 4 + m] = q0[n] * k0v[m] + q1[n] * k1v[m];
    #pragma unroll
    for (int off = 16; off > 0; off >>= 1)
        #pragma unroll
        for (int i = 0; i < 16; i++)
            s[i] += __shfl_xor_sync(0xffffffffu, s[i], off);

    float w[16];
    #pragma unroll
    for (int n = 0; n < 4; n++) {
        float p0 = s[n*4+0] * 0.125f, p1 = s[n*4+1] * 0.125f;
        float p2 = s[n*4+2] * 0.125f, p3 = s[n*4+3] * 0.125f;
        float mx = fmaxf(fmaxf(p0, p1), fmaxf(p2, p3));
        float e0 = __expf(p0 - mx), e1 = __expf(p1 - mx);
        float e2 = __expf(p2 - mx), e3 = __expf(p3 - mx);
        float inv = 1.0f / (e0 + e1 + e2 + e3);
        w[n*4+0] = e0 * inv; w[n*4+1] = e1 * inv;
        w[n*4+2] = e2 * inv; w[n*4+3] = e3 * inv;
    }
    float o0[4] = {0.f,0.f,0.f,0.f}, o1[4] = {0.f,0.f,0.f,0.f};
    #pragma unroll
    for (int m = 0; m < 4; m++) {
        float v0 = __half2float(base[512 + m * 64 + l]);
        float v1 = __half2float(base[512 + m * 64 + 32 + l]);
        #pragma unroll
        for (int n = 0; n < 4; n++) {
            o0[n] += w[n * 4 + m] * v0;
            o1[n] += w[n * 4 + m] * v1;
        }
    }
    size_t d = (size_t)t * C_;
    #pragma unroll
    for (int n = 0; n < 4; n++) {
        g_ah[d + n * 64 + l]      = __float2half_rn(o0[n]);
        g_ah[d + n * 64 + 32 + l] = __float2half_rn(o1[n]);
    }
}

// ============================================================================
// GEMM2 (fp16, 2-term, fused transpose): out[b,n,s] = sum_k attn[b,s,k]*wo[k,n]+bo[n]
//   A = attn fp16 [s][k] -> row-major tile, ldmatrix non-trans
//   B = wo hi/lo [k][n]  -> trans tiles
//   smem/stage: A@0 8KB, Bh@8192, Bl@16384 -> 24KB x2 stages.
// ============================================================================
__global__ __launch_bounds__(256) void gemm_out_mma(
    const float* __restrict__ bo, float* __restrict__ out)
{
    extern __shared__ __align__(16) char smem[];
    uint32_t sb = (uint32_t)__cvta_generic_to_shared(smem);

    int b  = blockIdx.z;
    int n0 = blockIdx.x * 128;
    int s0 = blockIdx.y * 128;
    const __half* ah_b = g_ah + (size_t)b * SEQ_ * C_;

    int tid = threadIdx.x, warp = tid >> 5, lane = tid & 31;
    int g = lane >> 2, tg = lane & 3;
    int wm = (warp & 1) * 64, wn = (warp >> 1) * 32;

    float acc[4][4][4];
    #pragma unroll
    for (int i = 0; i < 4; i++)
        #pragma unroll
        for (int j = 0; j < 4; j++)
            #pragma unroll
            for (int q = 0; q < 4; q++) acc[i][j][q] = 0.f;

    auto fill = [&](uint32_t st, int k0) {
        #pragma unroll
        for (int i = 0; i < 2; i++) {
            int idx2 = (i << 8) + tid;
            // A: 128 rows(s) x 32 k, 64B rows, 4 chunks, swizzle ch^((row>>1)&3)
            int rowA = idx2 >> 2, chA = idx2 & 3;
            uint32_t dA = rowA * 64 + ((chA ^ ((rowA >> 1) & 3)) << 4);
            cpa16(st + dA, ah_b + (size_t)(s0 + rowA) * C_ + k0 + chA * 8);
            // B: 32 rows(k) x 128 cols(n), 256B rows, swizzle ch^(row&7)
            int rowB = idx2 >> 4, chB = idx2 & 15;
            uint32_t dB = rowB * 256 + ((chB ^ (rowB & 7)) << 4);
            size_t sB_off = (size_t)(k0 + rowB) * C_ + n0 + chB * 8;
            cpa16(st + 8192  + dB, g_woh + sB_off);
            cpa16(st + 16384 + dB, g_wol + sB_off);
        }
    };

    fill(sb, 0);          CP_COMMIT();
    fill(sb + 24576, 32); CP_COMMIT();

    for (int kt = 0; kt < 8; kt++) {
        CP_WAIT1();
        __syncthreads();
        uint32_t sA = sb + (kt & 1) * 24576;
        uint32_t sB = sA + 8192;

        #pragma unroll
        for (int ks = 0; ks < 2; ks++) {
            uint32_t ah[4][4];
            #pragma unroll
            for (int mt = 0; mt < 4; mt++) {
                int row = wm + mt * 16 + (lane & 15);
                int ch  = ks * 2 + (lane >> 4);
                ldsm4(ah[mt], sA + row * 64 + ((ch ^ ((row >> 1) & 3)) << 4));
            }
            int rowb = ks * 16 + (lane & 7) + ((lane >> 4) << 3);
            int chs  = (lane >> 3) & 1;
            int rx   = rowb & 7;
            uint32_t rowoff = rowb * 256;
            uint32_t bh[4][2], bl[4][2];
            #pragma unroll
            for (int p = 0; p < 2; p++) {
                int ch = ((wn + p * 16) >> 3) + chs;
                uint32_t off = rowoff + ((ch ^ rx) << 4);
                uint32_t r[4], rl[4];
                ldsm4t(r,  sB + off);
                ldsm4t(rl, sB + 8192 + off);
                bh[2*p][0] = r[0];   bh[2*p][1] = r[2];
                bh[2*p+1][0] = r[1]; bh[2*p+1][1] = r[3];
                bl[2*p][0] = rl[0];  bl[2*p][1] = rl[2];
                bl[2*p+1][0] = rl[1]; bl[2*p+1][1] = rl[3];
            }
            #pragma unroll
            for (int mt = 0; mt < 4; mt++)
                #pragma unroll
                for (int nt = 0; nt < 4; nt++) {
                    mma_f16(acc[mt][nt], ah[mt], bh[nt]);
                    mma_f16(acc[mt][nt], ah[mt], bl[nt]);
                }
        }
        __syncthreads();
        if (kt < 6)
            fill(sb + (kt & 1) * 24576, (kt + 2) * 32);
        CP_COMMIT();
    }

    // fused-transpose epilogue
    float* ob = out + (size_t)b * C_ * SEQ_;
    #pragma unroll
    for (int nt = 0; nt < 4; nt++) {
        int c = n0 + wn + nt * 8 + 2 * tg;
        float b0 = bo[c], b1 = bo[c + 1];
        #pragma unroll
        for (int mt = 0; mt < 4; mt++) {
            int s = s0 + wm + mt * 16 + g;
            ob[(size_t)c       * SEQ_ + s]     = acc[mt][nt][0] + b0;
            ob[(size_t)(c + 1) * SEQ_ + s]     = acc[mt][nt][1] + b1;
            ob[(size_t)c       * SEQ_ + s + 8] = acc[mt][nt][2] + b0;
            ob[(size_t)(c + 1) * SEQ_ + s + 8] = acc[mt][nt][3] + b1;
        }
    }
}

// ============================================================================
extern "C" void kernel_launch(void* const* d_in, const int* in_sizes, int n_in,
                              void* d_out, int out_size)
{
    const float* x   = (const float*)d_in[0];
    const float* wq  = (const float*)d_in[1];
    const float* bq  = (const float*)d_in[2];
    const float* wkv = (const float*)d_in[3];
    const float* bkv = (const float*)d_in[4];
    const float* wo  = (const float*)d_in[5];
    const float* bo  = (const float*)d_in[6];
    float* out = (float*)d_out;

    static bool attr_set = false;
    if (!attr_set) {
        cudaFuncSetAttribute(gemm_qkv_mma,
            cudaFuncAttributeMaxDynamicSharedMemorySize, 65536);
        cudaFuncSetAttribute(gemm_out_mma,
            cudaFuncAttributeMaxDynamicSharedMemorySize, 49152);
        attr_set = true;
    }

    __half *xh, *woh, *wol;
    cudaGetSymbolAddress((void**)&xh,  g_xh);
    cudaGetSymbolAddress((void**)&woh, g_woh);
    cudaGetSymbolAddress((void**)&wol, g_wol);

    int nx4 = (B_ * C_ * SEQ_) / 4;
    conv_x<<<(nx4 + 255) / 256, 256>>>((const float4*)x, (uint2*)xh, nx4);
    int nw4 = (C_ * C_) / 4;
    split_wo4<<<(nw4 + 255) / 256, 256>>>((const float4*)wo,
                                          (uint2*)woh, (uint2*)wol, nw4);
    conv_wqkv<<<(C_ * NQKV) / 256, 256>>>(wq, wkv);

    gemm_qkv_mma<<<dim3(6, 32, 16), 256, 65536>>>(bq, bkv);
    attn_kernel<<<(B_ * SEQ_) / 8, 256>>>();
    gemm_out_mma<<<dim3(2, 32, 16), 256, 49152>>>(bo, out);
}